// round 10
// baseline (speedup 1.0000x reference)
#include <cuda_runtime.h>
#include <cuda_bf16.h>
#include <cuda_fp16.h>
#include <math.h>
#include <stdint.h>

// SoftEquivariantLayer v9: v8 pipeline (bf16 HMMA mixing GEMM + fp16 HMMA MLP
// layer-2, fragment-packed weights) at 1024 threads: 16 GEMM warps (16x64 tiles)
// + 16 MLP warps (8 rows each). Halves every per-warp serial chain.

#define ROWS    128
#define THREADS 1024

// ---- SMEM byte offsets ----
#define ZF_B    0          // Z fp32 [128][132] row-major       (67584)
#define ZH_B    67584      // Z bf16 [128] rows, 272B stride    (34816)
#define WH_B    102400     // packed mixing B frags bf16        (32768)
#define H1H_B   135168     // h1 fp16 [128] rows, 144B stride   (18432)
#define W2H_B   153600     // packed w2 frags fp16              (8192)
#define W3T_B   161792     // w3^T [64][8] f32                  (2048)
#define W1_B    163840     // [64][8] f32                       (2048)
#define B1_B    165888     // 256
#define B2_B    166144     // 256
#define G_B     166400     // 32
#define SC_B    166432     // scales [128][8] f32               (4096)
#define SMEM_BYTES 170528

__device__ __nv_bfloat16 gWpk[16384];   // mix_w: bf16, fragment-packed
__device__ __half        gW2pk[4096];   // w2: fp16, fragment-packed

// ---------------- helpers ----------------
static __device__ __forceinline__ uint32_t s2u(const void* p) {
    uint32_t a;
    asm("{ .reg .u64 t; cvta.to.shared.u64 t, %1; cvt.u32.u64 %0, t; }" : "=r"(a) : "l"(p));
    return a;
}
static __device__ __forceinline__ float gelu_fast(float x) {
    float t = fabsf(x) * 0.7071067811865476f;
    float u = __fdividef(1.0f, fmaf(0.3275911f, t, 1.0f));
    float poly = u * fmaf(u, fmaf(u, fmaf(u, fmaf(u, 1.061405429f, -1.453152027f),
                                          1.421413741f), -0.284496736f), 0.254829592f);
    float e = __expf(-t * t);
    float erfv = fmaf(-poly, e, 1.0f);
    return x * 0.5f * (1.0f + copysignf(erfv, x));
}
static __device__ __forceinline__ float softplus_fast(float x) {
    float e = __expf(-fabsf(x));
    float l = __logf(1.0f + e);
    return x > 0.0f ? x + l : l;
}
static __device__ __forceinline__ void mma16bf(float4& d, uint32_t a0, uint32_t a1,
                                               uint32_t a2, uint32_t a3,
                                               uint32_t b0, uint32_t b1) {
    asm volatile("mma.sync.aligned.m16n8k16.row.col.f32.bf16.bf16.f32 "
                 "{%0,%1,%2,%3}, {%4,%5,%6,%7}, {%8,%9}, {%0,%1,%2,%3};"
                 : "+f"(d.x), "+f"(d.y), "+f"(d.z), "+f"(d.w)
                 : "r"(a0), "r"(a1), "r"(a2), "r"(a3), "r"(b0), "r"(b1));
}
static __device__ __forceinline__ void mma16h(float4& d, uint32_t a0, uint32_t a1,
                                              uint32_t a2, uint32_t a3,
                                              uint32_t b0, uint32_t b1) {
    asm volatile("mma.sync.aligned.m16n8k16.row.col.f32.f16.f16.f32 "
                 "{%0,%1,%2,%3}, {%4,%5,%6,%7}, {%8,%9}, {%0,%1,%2,%3};"
                 : "+f"(d.x), "+f"(d.y), "+f"(d.z), "+f"(d.w)
                 : "r"(a0), "r"(a1), "r"(a2), "r"(a3), "r"(b0), "r"(b1));
}
static __device__ __forceinline__ void ldsm4(uint32_t& r0, uint32_t& r1,
                                             uint32_t& r2, uint32_t& r3, uint32_t addr) {
    asm volatile("ldmatrix.sync.aligned.m8n8.x4.shared.b16 {%0,%1,%2,%3}, [%4];"
                 : "=r"(r0), "=r"(r1), "=r"(r2), "=r"(r3) : "r"(addr));
}

// ---------------- prep kernels (validated layouts) ----------------
__global__ void prep_kernel(const float* __restrict__ mixw) {
    int g = blockIdx.x * 256 + threadIdx.x;
    int i = g >> 11, j = (g >> 8) & 7, k = (g >> 4) & 15, d = g & 15;
    int n  = i * 16 + k;
    int kd = j * 16 + d;
    int nh = n >> 6, nt = (n >> 3) & 7, qt = n & 7;
    int ks = kd >> 4, kr = kd & 15;
    int b  = kr >> 3, qc = (kr & 7) >> 1, h = kr & 1;
    int lid = qt * 4 + qc;
    int idx = nh * 8192 + ks * 1024 + (nt >> 1) * 256 + lid * 8 + (nt & 1) * 4 + b * 2 + h;
    gWpk[idx] = __float2bfloat16(mixw[g]);
}
__global__ void prep2_kernel(const float* __restrict__ w2) {
    int g = blockIdx.x * 256 + threadIdx.x;
    int o = g >> 6;
    int i = g & 63;
    int nt = o >> 3, qt = o & 7;
    int ks = i >> 4, kr = i & 15;
    int b  = kr >> 3, qc = (kr & 7) >> 1, h = kr & 1;
    int lid = qt * 4 + qc;
    int idx = ks * 1024 + (nt >> 1) * 256 + lid * 8 + (nt & 1) * 4 + b * 2 + h;
    gW2pk[idx] = __float2half_rn(w2[g]);
}

// ---------------- main fused kernel ----------------
__global__ void __launch_bounds__(THREADS, 1)
soft_equivariant_kernel(const float* __restrict__ z,
                        const float* __restrict__ w1,
                        const float* __restrict__ b1,
                        const float* __restrict__ b2,
                        const float* __restrict__ w3,
                        const float* __restrict__ gb,
                        float* __restrict__ out)
{
    extern __shared__ char smem[];
    float* Zf  = (float*)(smem + ZF_B);
    float* w3t = (float*)(smem + W3T_B);
    float* w1s = (float*)(smem + W1_B);
    float* b1s = (float*)(smem + B1_B);
    float* b2s = (float*)(smem + B2_B);
    float* gts = (float*)(smem + G_B);
    float* scs = (float*)(smem + SC_B);

    const int tid = threadIdx.x;
    const int wid = tid >> 5;
    const int lid = tid & 31;
    const int row0 = blockIdx.x * ROWS;
    const uint32_t smb = s2u(smem);

    // ---- cooperative loads ----
    {
        if (tid < 512) {
            w1s[tid] = w1[tid];
            int j = tid >> 6, col = tid & 63;
            w3t[col * 8 + j] = w3[tid];
        }
        if (tid < 64) { b1s[tid] = b1[tid]; b2s[tid] = b2[tid]; }
        if (tid < 8)  gts[tid] = 1.0f / (1.0f + __expf(-gb[tid]));
    }
    {   // packed mixing B: 32KB + packed w2: 8KB
        const float4* s = (const float4*)gWpk;
        float4* d4 = (float4*)(smem + WH_B);
        d4[tid] = s[tid];
        d4[tid + 1024] = s[tid + 1024];
        if (tid < 512) {
            ((float4*)(smem + W2H_B))[tid] = ((const float4*)gW2pk)[tid];
        }
    }
    {   // z: fp32 row-major + bf16 copy (272B stride)
        const float4* zg = (const float4*)(z + (size_t)row0 * 128);
        #pragma unroll
        for (int e = 0; e < 4; ++e) {
            int idx = e * THREADS + tid;
            int row = idx >> 5;
            int c4  = idx & 31;
            float4 v = zg[idx];
            *(float4*)(Zf + row * 132 + c4 * 4) = v;
            __nv_bfloat162 p0 = __floats2bfloat162_rn(v.x, v.y);
            __nv_bfloat162 p1 = __floats2bfloat162_rn(v.z, v.w);
            uint2 pr = make_uint2(*(uint32_t*)&p0, *(uint32_t*)&p1);
            *(uint2*)(smem + ZH_B + row * 272 + c4 * 8) = pr;
        }
    }
    __syncthreads();

    if (wid < 16) {
        // ========== GEMM warps: bf16 m16n8k16, 16x64 tile each ================
        const int mw = wid & 7;        // rows mw*16..
        const int nh = wid >> 3;       // cols nh*64..
        const int qt = lid >> 2;
        const int qc = lid & 3;

        float4 acc[8];
        #pragma unroll
        for (int nt = 0; nt < 8; ++nt) acc[nt] = make_float4(0.f, 0.f, 0.f, 0.f);

        const int lm_row = ((lid >> 3) & 1) * 8 + (lid & 7);
        const int lm_col = (lid >> 4) * 16;
        const uint32_t abase = smb + ZH_B + (mw * 16 + lm_row) * 272 + lm_col;
        const char* wbase = smem + WH_B + nh * 16384;

        #pragma unroll
        for (int ks = 0; ks < 8; ++ks) {
            uint32_t a0, a1, a2, a3;
            ldsm4(a0, a1, a2, a3, abase + ks * 32);
            const char* wp = wbase + ks * 2048 + lid * 16;
            uint4 l0 = *(const uint4*)(wp);
            uint4 l1 = *(const uint4*)(wp + 512);
            uint4 l2 = *(const uint4*)(wp + 1024);
            uint4 l3 = *(const uint4*)(wp + 1536);
            mma16bf(acc[0], a0, a1, a2, a3, l0.x, l0.y);
            mma16bf(acc[1], a0, a1, a2, a3, l0.z, l0.w);
            mma16bf(acc[2], a0, a1, a2, a3, l1.x, l1.y);
            mma16bf(acc[3], a0, a1, a2, a3, l1.z, l1.w);
            mma16bf(acc[4], a0, a1, a2, a3, l2.x, l2.y);
            mma16bf(acc[5], a0, a1, a2, a3, l2.z, l2.w);
            mma16bf(acc[6], a0, a1, a2, a3, l3.x, l3.y);
            mma16bf(acc[7], a0, a1, a2, a3, l3.z, l3.w);
        }
        __syncthreads();     // wait for MLP warps' scales

        // ---- epilogue ----
        #pragma unroll
        for (int nt = 0; nt < 8; ++nt) {
            const int bundle = nh * 4 + (nt >> 1);
            const float g = gts[bundle];
            const int x0 = nh * 64 + nt * 8 + 2 * qc;
            #pragma unroll
            for (int rh = 0; rh < 2; ++rh) {
                const int r = mw * 16 + rh * 8 + qt;
                const float s1 = 1.0f + scs[r * 8 + bundle];
                float2 zv = *(const float2*)(Zf + r * 132 + x0);
                float m0 = (rh == 0) ? acc[nt].x : acc[nt].z;
                float m1 = (rh == 0) ? acc[nt].y : acc[nt].w;
                float2 o = make_float2(zv.x * s1 + g * m0, zv.y * s1 + g * m1);
                *(float2*)(out + (size_t)(row0 + r) * 128 + x0) = o;
            }
        }
    } else {
        // ========== MLP warps: each owns 8 rows, fully warp-independent ========
        const int u = wid - 16;           // 0..15
        const int r0 = u * 8;
        const int lrow = lid >> 2;        // 0..7
        const int c = lid & 3;            // quarter split (k and outputs)
        const int row = r0 + lrow;
        const float4* Z4 = (const float4*)Zf;   // 33 float4 per row

        // ---- norms: lane covers 1 float4 per bundle; quad reduce ----
        float pn[8];
        #pragma unroll
        for (int j = 0; j < 8; ++j) {
            float4 v = Z4[row * 33 + j * 4 + c];
            pn[j] = v.x * v.x + v.y * v.y + v.z * v.z + v.w * v.w;
        }
        float nrm[8];
        #pragma unroll
        for (int j = 0; j < 8; ++j) {
            pn[j] += __shfl_xor_sync(0xffffffffu, pn[j], 1);
            pn[j] += __shfl_xor_sync(0xffffffffu, pn[j], 2);
            nrm[j] = sqrtf(pn[j]) + 1e-8f;
        }

        // ---- layer 1: lane computes 16 outputs (quarter-split), store fp16 ----
        {
            char* hrow = smem + H1H_B + row * 144 + c * 32;
            #pragma unroll
            for (int q = 0; q < 2; ++q) {        // 8 outputs per q -> one STS.128
                uint32_t pk[4];
                #pragma unroll
                for (int s = 0; s < 4; ++s) {
                    int o = c * 16 + q * 8 + 2 * s;
                    const float4* wr = (const float4*)(w1s + o * 8);
                    float4 wa = wr[0], wb = wr[1];
                    float a0 = b1s[o];
                    a0 += nrm[0] * wa.x + nrm[1] * wa.y + nrm[2] * wa.z + nrm[3] * wa.w;
                    a0 += nrm[4] * wb.x + nrm[5] * wb.y + nrm[6] * wb.z + nrm[7] * wb.w;
                    const float4* wr2 = (const float4*)(w1s + (o + 1) * 8);
                    float4 wc = wr2[0], wd = wr2[1];
                    float a1 = b1s[o + 1];
                    a1 += nrm[0] * wc.x + nrm[1] * wc.y + nrm[2] * wc.z + nrm[3] * wc.w;
                    a1 += nrm[4] * wd.x + nrm[5] * wd.y + nrm[6] * wd.z + nrm[7] * wd.w;
                    __half2 hh = __floats2half2_rn(gelu_fast(a0), gelu_fast(a1));
                    pk[s] = *(uint32_t*)&hh;
                }
                *(uint4*)(hrow + q * 16) = make_uint4(pk[0], pk[1], pk[2], pk[3]);
            }
        }
        __syncwarp();

        // ---- layer 2: fp16 m16n8k16, A rows duplicated (8 real rows) ----
        const int qt = lid >> 2;
        const int qc4 = lid & 3;
        float4 acc[8];
        #pragma unroll
        for (int nt = 0; nt < 8; ++nt) acc[nt] = make_float4(0.f, 0.f, 0.f, 0.f);

        {
            const int lm_row = lid & 7;              // duplicate rows 0-7 into 8-15
            const int lm_col = (lid >> 4) * 16;
            const uint32_t abase = smb + H1H_B + (r0 + lm_row) * 144 + lm_col;
            const char* wbase = smem + W2H_B;
            #pragma unroll
            for (int ks = 0; ks < 4; ++ks) {
                uint32_t a0, a1, a2, a3;
                ldsm4(a0, a1, a2, a3, abase + ks * 32);
                const char* wp = wbase + ks * 2048 + lid * 16;
                uint4 l0 = *(const uint4*)(wp);
                uint4 l1 = *(const uint4*)(wp + 512);
                uint4 l2 = *(const uint4*)(wp + 1024);
                uint4 l3 = *(const uint4*)(wp + 1536);
                mma16h(acc[0], a0, a1, a2, a3, l0.x, l0.y);
                mma16h(acc[1], a0, a1, a2, a3, l0.z, l0.w);
                mma16h(acc[2], a0, a1, a2, a3, l1.x, l1.y);
                mma16h(acc[3], a0, a1, a2, a3, l1.z, l1.w);
                mma16h(acc[4], a0, a1, a2, a3, l2.x, l2.y);
                mma16h(acc[5], a0, a1, a2, a3, l2.z, l2.w);
                mma16h(acc[6], a0, a1, a2, a3, l3.x, l3.y);
                mma16h(acc[7], a0, a1, a2, a3, l3.z, l3.w);
            }
        }

        // ---- bias + gelu on fragments (rows qt only); layer-3 partials ----
        float s0[8];
        #pragma unroll
        for (int j = 0; j < 8; ++j) s0[j] = 0.0f;
        #pragma unroll
        for (int nt = 0; nt < 8; ++nt) {
            int c0 = nt * 8 + 2 * qc4;
            float h00 = gelu_fast(acc[nt].x + b2s[c0]);
            float h01 = gelu_fast(acc[nt].y + b2s[c0 + 1]);
            const float4* wa = (const float4*)(w3t + c0 * 8);
            const float4* wb = (const float4*)(w3t + (c0 + 1) * 8);
            float4 wa0 = wa[0], wa1 = wa[1], wb0 = wb[0], wb1 = wb[1];
            s0[0] += h00 * wa0.x + h01 * wb0.x;  s0[1] += h00 * wa0.y + h01 * wb0.y;
            s0[2] += h00 * wa0.z + h01 * wb0.z;  s0[3] += h00 * wa0.w + h01 * wb0.w;
            s0[4] += h00 * wa1.x + h01 * wb1.x;  s0[5] += h00 * wa1.y + h01 * wb1.y;
            s0[6] += h00 * wa1.z + h01 * wb1.z;  s0[7] += h00 * wa1.w + h01 * wb1.w;
        }
        #pragma unroll
        for (int j = 0; j < 8; ++j) {
            s0[j] += __shfl_xor_sync(0xffffffffu, s0[j], 1);
            s0[j] += __shfl_xor_sync(0xffffffffu, s0[j], 2);
        }
        if (qc4 == 0) {
            float* d0 = scs + (r0 + qt) * 8;
            *(float4*)(d0)     = make_float4(softplus_fast(s0[0]), softplus_fast(s0[1]),
                                             softplus_fast(s0[2]), softplus_fast(s0[3]));
            *(float4*)(d0 + 4) = make_float4(softplus_fast(s0[4]), softplus_fast(s0[5]),
                                             softplus_fast(s0[6]), softplus_fast(s0[7]));
        }
        __syncthreads();     // release GEMM warps into epilogue
    }
}

extern "C" void kernel_launch(void* const* d_in, const int* in_sizes, int n_in,
                              void* d_out, int out_size)
{
    const float* z    = (const float*)d_in[0];
    const float* w1   = (const float*)d_in[1];
    const float* b1   = (const float*)d_in[2];
    const float* w2   = (const float*)d_in[3];
    const float* b2   = (const float*)d_in[4];
    const float* w3   = (const float*)d_in[5];
    const float* mixw = (const float*)d_in[6];
    const float* gb   = (const float*)d_in[7];
    float* out = (float*)d_out;

    int Btot = in_sizes[0] / 128;            // 524288 rows
    int nblocks = Btot / ROWS;               // 4096

    prep_kernel<<<64, 256>>>(mixw);
    prep2_kernel<<<16, 256>>>(w2);

    static bool attr_set = false;
    if (!attr_set) {
        cudaFuncSetAttribute(soft_equivariant_kernel,
                             cudaFuncAttributeMaxDynamicSharedMemorySize, SMEM_BYTES);
        attr_set = true;
    }
    soft_equivariant_kernel<<<nblocks, THREADS, SMEM_BYTES>>>(
        z, w1, b1, b2, w3, gb, out);
}

// round 11
// speedup vs baseline: 2.2521x; 2.2521x over previous
#include <cuda_runtime.h>
#include <cuda_bf16.h>
#include <cuda_fp16.h>
#include <math.h>
#include <stdint.h>

// SoftEquivariantLayer v10: v8 pipeline (512 threads, bf16 HMMA mixing GEMM +
// fp16 HMMA MLP layer-2, fragment-packed weights; measured 273us) wrapped in a
// 4-tile persistent loop: grid 1024, weights staged once per CTA, uniform
// barriers hoisted out of the warp-role branches.

#define ROWS    128
#define TILES   4
#define THREADS 512

// ---- SMEM byte offsets ----
#define ZF_B    0          // Z fp32 [128][132] row-major       (67584)
#define ZH_B    67584      // Z bf16 [128] rows, 272B stride    (34816)
#define WH_B    102400     // packed mixing B frags bf16        (32768)
#define H1H_B   135168     // h1 fp16 [128] rows, 144B stride   (18432)
#define W2H_B   153600     // packed w2 frags fp16              (8192)
#define W3T_B   161792     // w3^T [64][8] f32                  (2048)
#define W1_B    163840     // [64][8] f32                       (2048)
#define B1_B    165888     // 256
#define B2_B    166144     // 256
#define G_B     166400     // 32
#define SC_B    166432     // scales [128][8] f32               (4096)
#define SMEM_BYTES 170528

__device__ __nv_bfloat16 gWpk[16384];   // mix_w: bf16, fragment-packed
__device__ __half        gW2pk[4096];   // w2: fp16, fragment-packed

// ---------------- helpers ----------------
static __device__ __forceinline__ uint32_t s2u(const void* p) {
    uint32_t a;
    asm("{ .reg .u64 t; cvta.to.shared.u64 t, %1; cvt.u32.u64 %0, t; }" : "=r"(a) : "l"(p));
    return a;
}
static __device__ __forceinline__ float gelu_fast(float x) {
    float t = fabsf(x) * 0.7071067811865476f;
    float u = __fdividef(1.0f, fmaf(0.3275911f, t, 1.0f));
    float poly = u * fmaf(u, fmaf(u, fmaf(u, fmaf(u, 1.061405429f, -1.453152027f),
                                          1.421413741f), -0.284496736f), 0.254829592f);
    float e = __expf(-t * t);
    float erfv = fmaf(-poly, e, 1.0f);
    return x * 0.5f * (1.0f + copysignf(erfv, x));
}
static __device__ __forceinline__ float softplus_fast(float x) {
    float e = __expf(-fabsf(x));
    float l = __logf(1.0f + e);
    return x > 0.0f ? x + l : l;
}
static __device__ __forceinline__ void mma16bf(float4& d, uint32_t a0, uint32_t a1,
                                               uint32_t a2, uint32_t a3,
                                               uint32_t b0, uint32_t b1) {
    asm volatile("mma.sync.aligned.m16n8k16.row.col.f32.bf16.bf16.f32 "
                 "{%0,%1,%2,%3}, {%4,%5,%6,%7}, {%8,%9}, {%0,%1,%2,%3};"
                 : "+f"(d.x), "+f"(d.y), "+f"(d.z), "+f"(d.w)
                 : "r"(a0), "r"(a1), "r"(a2), "r"(a3), "r"(b0), "r"(b1));
}
static __device__ __forceinline__ void mma16h(float4& d, uint32_t a0, uint32_t a1,
                                              uint32_t a2, uint32_t a3,
                                              uint32_t b0, uint32_t b1) {
    asm volatile("mma.sync.aligned.m16n8k16.row.col.f32.f16.f16.f32 "
                 "{%0,%1,%2,%3}, {%4,%5,%6,%7}, {%8,%9}, {%0,%1,%2,%3};"
                 : "+f"(d.x), "+f"(d.y), "+f"(d.z), "+f"(d.w)
                 : "r"(a0), "r"(a1), "r"(a2), "r"(a3), "r"(b0), "r"(b1));
}
static __device__ __forceinline__ void ldsm4(uint32_t& r0, uint32_t& r1,
                                             uint32_t& r2, uint32_t& r3, uint32_t addr) {
    asm volatile("ldmatrix.sync.aligned.m8n8.x4.shared.b16 {%0,%1,%2,%3}, [%4];"
                 : "=r"(r0), "=r"(r1), "=r"(r2), "=r"(r3) : "r"(addr));
}

// ---------------- prep kernels (validated layouts) ----------------
__global__ void prep_kernel(const float* __restrict__ mixw) {
    int g = blockIdx.x * 256 + threadIdx.x;
    int i = g >> 11, j = (g >> 8) & 7, k = (g >> 4) & 15, d = g & 15;
    int n  = i * 16 + k;
    int kd = j * 16 + d;
    int nh = n >> 6, nt = (n >> 3) & 7, qt = n & 7;
    int ks = kd >> 4, kr = kd & 15;
    int b  = kr >> 3, qc = (kr & 7) >> 1, h = kr & 1;
    int lid = qt * 4 + qc;
    int idx = nh * 8192 + ks * 1024 + (nt >> 1) * 256 + lid * 8 + (nt & 1) * 4 + b * 2 + h;
    gWpk[idx] = __float2bfloat16(mixw[g]);
}
__global__ void prep2_kernel(const float* __restrict__ w2) {
    int g = blockIdx.x * 256 + threadIdx.x;
    int o = g >> 6;
    int i = g & 63;
    int nt = o >> 3, qt = o & 7;
    int ks = i >> 4, kr = i & 15;
    int b  = kr >> 3, qc = (kr & 7) >> 1, h = kr & 1;
    int lid = qt * 4 + qc;
    int idx = ks * 1024 + (nt >> 1) * 256 + lid * 8 + (nt & 1) * 4 + b * 2 + h;
    gW2pk[idx] = __float2half_rn(w2[g]);
}

// ---------------- main fused kernel ----------------
__global__ void __launch_bounds__(THREADS, 1)
soft_equivariant_kernel(const float* __restrict__ z,
                        const float* __restrict__ w1,
                        const float* __restrict__ b1,
                        const float* __restrict__ b2,
                        const float* __restrict__ w3,
                        const float* __restrict__ gb,
                        float* __restrict__ out)
{
    extern __shared__ char smem[];
    float* Zf  = (float*)(smem + ZF_B);
    float* w3t = (float*)(smem + W3T_B);
    float* w1s = (float*)(smem + W1_B);
    float* b1s = (float*)(smem + B1_B);
    float* b2s = (float*)(smem + B2_B);
    float* gts = (float*)(smem + G_B);
    float* scs = (float*)(smem + SC_B);

    const int tid = threadIdx.x;
    const int wid = tid >> 5;
    const int lid = tid & 31;
    const uint32_t smb = s2u(smem);

    // ---- one-time staging: weights + packed fragments ----
    {
        w1s[tid] = w1[tid];
        { int j = tid >> 6, col = tid & 63; w3t[col * 8 + j] = w3[tid]; }
        if (tid < 64) { b1s[tid] = b1[tid]; b2s[tid] = b2[tid]; }
        if (tid < 8)  gts[tid] = 1.0f / (1.0f + __expf(-gb[tid]));
        const float4* s = (const float4*)gWpk;
        float4* d4 = (float4*)(smem + WH_B);
        #pragma unroll
        for (int e = 0; e < 4; ++e) d4[e * THREADS + tid] = s[e * THREADS + tid];
        const float4* s2 = (const float4*)gW2pk;
        ((float4*)(smem + W2H_B))[tid] = s2[tid];
    }

    for (int t = 0; t < TILES; ++t) {
        const int row0 = (blockIdx.x * TILES + t) * ROWS;

        // ---- Z staging: fp32 row-major + bf16 copy (272B stride) ----
        {
            const float4* zg = (const float4*)(z + (size_t)row0 * 128);
            #pragma unroll
            for (int e = 0; e < 8; ++e) {
                int idx = e * THREADS + tid;
                int row = idx >> 5;
                int c4  = idx & 31;
                float4 v = zg[idx];
                *(float4*)(Zf + row * 132 + c4 * 4) = v;
                __nv_bfloat162 p0 = __floats2bfloat162_rn(v.x, v.y);
                __nv_bfloat162 p1 = __floats2bfloat162_rn(v.z, v.w);
                uint2 pr = make_uint2(*(uint32_t*)&p0, *(uint32_t*)&p1);
                *(uint2*)(smem + ZH_B + row * 272 + c4 * 8) = pr;
            }
        }
        __syncthreads();

        float4 acc[8];           // GEMM warps: mixing tile; (MLP warps reuse name below)

        if (wid < 8) {
            // ========== GEMM warps: bf16 m16n8k16, 32x64 tile each ============
            const int mw = wid & 3;
            const int nh = wid >> 2;

            float4 acc2[8];
            #pragma unroll
            for (int nt = 0; nt < 8; ++nt) {
                acc[nt] = make_float4(0.f, 0.f, 0.f, 0.f);
                acc2[nt] = make_float4(0.f, 0.f, 0.f, 0.f);
            }

            const int lm_row = ((lid >> 3) & 1) * 8 + (lid & 7);
            const int lm_col = (lid >> 4) * 16;
            const uint32_t abase = smb + ZH_B + (mw * 32 + lm_row) * 272 + lm_col;
            const char* wbase = smem + WH_B + nh * 16384;

            #pragma unroll
            for (int ks = 0; ks < 8; ++ks) {
                uint32_t a0, a1, a2, a3, c0, c1, c2, c3;
                ldsm4(a0, a1, a2, a3, abase + ks * 32);
                ldsm4(c0, c1, c2, c3, abase + 16 * 272 + ks * 32);
                const char* wp = wbase + ks * 2048 + lid * 16;
                uint4 l0 = *(const uint4*)(wp);
                uint4 l1 = *(const uint4*)(wp + 512);
                uint4 l2 = *(const uint4*)(wp + 1024);
                uint4 l3 = *(const uint4*)(wp + 1536);
                mma16bf(acc[0], a0, a1, a2, a3, l0.x, l0.y);
                mma16bf(acc[1], a0, a1, a2, a3, l0.z, l0.w);
                mma16bf(acc[2], a0, a1, a2, a3, l1.x, l1.y);
                mma16bf(acc[3], a0, a1, a2, a3, l1.z, l1.w);
                mma16bf(acc[4], a0, a1, a2, a3, l2.x, l2.y);
                mma16bf(acc[5], a0, a1, a2, a3, l2.z, l2.w);
                mma16bf(acc[6], a0, a1, a2, a3, l3.x, l3.y);
                mma16bf(acc[7], a0, a1, a2, a3, l3.z, l3.w);
                mma16bf(acc2[0], c0, c1, c2, c3, l0.x, l0.y);
                mma16bf(acc2[1], c0, c1, c2, c3, l0.z, l0.w);
                mma16bf(acc2[2], c0, c1, c2, c3, l1.x, l1.y);
                mma16bf(acc2[3], c0, c1, c2, c3, l1.z, l1.w);
                mma16bf(acc2[4], c0, c1, c2, c3, l2.x, l2.y);
                mma16bf(acc2[5], c0, c1, c2, c3, l2.z, l2.w);
                mma16bf(acc2[6], c0, c1, c2, c3, l3.x, l3.y);
                mma16bf(acc2[7], c0, c1, c2, c3, l3.z, l3.w);
            }
            __syncthreads();     // [scales barrier] wait for MLP warps

            // ---- epilogue (both 16-row halves) ----
            const int qt = lid >> 2;
            const int qc = lid & 3;
            #pragma unroll
            for (int nt = 0; nt < 8; ++nt) {
                const int bundle = nh * 4 + (nt >> 1);
                const float g = gts[bundle];
                const int x0 = nh * 64 + nt * 8 + 2 * qc;
                #pragma unroll
                for (int mt = 0; mt < 2; ++mt) {
                    float4 a = (mt == 0) ? acc[nt] : acc2[nt];
                    #pragma unroll
                    for (int rh = 0; rh < 2; ++rh) {
                        const int r = mw * 32 + mt * 16 + rh * 8 + qt;
                        const float s1 = 1.0f + scs[r * 8 + bundle];
                        float2 zv = *(const float2*)(Zf + r * 132 + x0);
                        float m0 = (rh == 0) ? a.x : a.z;
                        float m1 = (rh == 0) ? a.y : a.w;
                        float2 o = make_float2(zv.x * s1 + g * m0, zv.y * s1 + g * m1);
                        *(float2*)(out + (size_t)(row0 + r) * 128 + x0) = o;
                    }
                }
            }
        } else {
            // ========== MLP warps: each owns 16 rows, warp-independent ========
            const int u = wid - 8;
            const int r0 = u * 16;
            const int lrow = lid >> 1;
            const int half = lid & 1;
            const int row = r0 + lrow;
            const float4* Z4 = (const float4*)Zf;

            // ---- norms ----
            float pn[8];
            #pragma unroll
            for (int j = 0; j < 8; ++j) pn[j] = 0.0f;
            #pragma unroll
            for (int cc = 0; cc < 2; ++cc) {
                #pragma unroll
                for (int j = 0; j < 8; ++j) {
                    float4 v = Z4[row * 33 + j * 4 + 2 * half + cc];
                    pn[j] += v.x * v.x + v.y * v.y + v.z * v.z + v.w * v.w;
                }
            }
            float nrm[8];
            #pragma unroll
            for (int j = 0; j < 8; ++j) {
                float o = __shfl_xor_sync(0xffffffffu, pn[j], 1);
                nrm[j] = sqrtf(pn[j] + o) + 1e-8f;
            }

            // ---- layer 1 (32 outputs per lane, half-split), store fp16 ----
            {
                char* hrow = smem + H1H_B + row * 144 + half * 64;
                #pragma unroll
                for (int q = 0; q < 4; ++q) {
                    uint32_t pk[4];
                    #pragma unroll
                    for (int s = 0; s < 4; ++s) {
                        int o = half * 32 + q * 8 + 2 * s;
                        const float4* wr = (const float4*)(w1s + o * 8);
                        float4 wa = wr[0], wb = wr[1];
                        float a0 = b1s[o];
                        a0 += nrm[0] * wa.x + nrm[1] * wa.y + nrm[2] * wa.z + nrm[3] * wa.w;
                        a0 += nrm[4] * wb.x + nrm[5] * wb.y + nrm[6] * wb.z + nrm[7] * wb.w;
                        const float4* wr2 = (const float4*)(w1s + (o + 1) * 8);
                        float4 wc = wr2[0], wd = wr2[1];
                        float a1 = b1s[o + 1];
                        a1 += nrm[0] * wc.x + nrm[1] * wc.y + nrm[2] * wc.z + nrm[3] * wc.w;
                        a1 += nrm[4] * wd.x + nrm[5] * wd.y + nrm[6] * wd.z + nrm[7] * wd.w;
                        __half2 hh = __floats2half2_rn(gelu_fast(a0), gelu_fast(a1));
                        pk[s] = *(uint32_t*)&hh;
                    }
                    *(uint4*)(hrow + q * 16) = make_uint4(pk[0], pk[1], pk[2], pk[3]);
                }
            }
            __syncwarp();

            // ---- layer 2: fp16 m16n8k16 ----
            const int qt = lid >> 2;
            const int qc = lid & 3;
            #pragma unroll
            for (int nt = 0; nt < 8; ++nt) acc[nt] = make_float4(0.f, 0.f, 0.f, 0.f);
            {
                const int lm_row = ((lid >> 3) & 1) * 8 + (lid & 7);
                const int lm_col = (lid >> 4) * 16;
                const uint32_t abase = smb + H1H_B + (r0 + lm_row) * 144 + lm_col;
                const char* wbase = smem + W2H_B;
                #pragma unroll
                for (int ks = 0; ks < 4; ++ks) {
                    uint32_t a0, a1, a2, a3;
                    ldsm4(a0, a1, a2, a3, abase + ks * 32);
                    const char* wp = wbase + ks * 2048 + lid * 16;
                    uint4 l0 = *(const uint4*)(wp);
                    uint4 l1 = *(const uint4*)(wp + 512);
                    uint4 l2 = *(const uint4*)(wp + 1024);
                    uint4 l3 = *(const uint4*)(wp + 1536);
                    mma16h(acc[0], a0, a1, a2, a3, l0.x, l0.y);
                    mma16h(acc[1], a0, a1, a2, a3, l0.z, l0.w);
                    mma16h(acc[2], a0, a1, a2, a3, l1.x, l1.y);
                    mma16h(acc[3], a0, a1, a2, a3, l1.z, l1.w);
                    mma16h(acc[4], a0, a1, a2, a3, l2.x, l2.y);
                    mma16h(acc[5], a0, a1, a2, a3, l2.z, l2.w);
                    mma16h(acc[6], a0, a1, a2, a3, l3.x, l3.y);
                    mma16h(acc[7], a0, a1, a2, a3, l3.z, l3.w);
                }
            }

            // ---- bias + gelu; layer-3 partials; quad reduce; softplus ----
            float s0[8], s1[8];
            #pragma unroll
            for (int j = 0; j < 8; ++j) { s0[j] = 0.0f; s1[j] = 0.0f; }
            #pragma unroll
            for (int nt = 0; nt < 8; ++nt) {
                int c0 = nt * 8 + 2 * qc;
                float bb0 = b2s[c0], bb1 = b2s[c0 + 1];
                float h00 = gelu_fast(acc[nt].x + bb0);
                float h01 = gelu_fast(acc[nt].y + bb1);
                float h10 = gelu_fast(acc[nt].z + bb0);
                float h11 = gelu_fast(acc[nt].w + bb1);
                const float4* wa = (const float4*)(w3t + c0 * 8);
                const float4* wb = (const float4*)(w3t + (c0 + 1) * 8);
                float4 wa0 = wa[0], wa1 = wa[1], wb0 = wb[0], wb1 = wb[1];
                s0[0] += h00 * wa0.x + h01 * wb0.x;  s0[1] += h00 * wa0.y + h01 * wb0.y;
                s0[2] += h00 * wa0.z + h01 * wb0.z;  s0[3] += h00 * wa0.w + h01 * wb0.w;
                s0[4] += h00 * wa1.x + h01 * wb1.x;  s0[5] += h00 * wa1.y + h01 * wb1.y;
                s0[6] += h00 * wa1.z + h01 * wb1.z;  s0[7] += h00 * wa1.w + h01 * wb1.w;
                s1[0] += h10 * wa0.x + h11 * wb0.x;  s1[1] += h10 * wa0.y + h11 * wb0.y;
                s1[2] += h10 * wa0.z + h11 * wb0.z;  s1[3] += h10 * wa0.w + h11 * wb0.w;
                s1[4] += h10 * wa1.x + h11 * wb1.x;  s1[5] += h10 * wa1.y + h11 * wb1.y;
                s1[6] += h10 * wa1.z + h11 * wb1.z;  s1[7] += h10 * wa1.w + h11 * wb1.w;
            }
            #pragma unroll
            for (int j = 0; j < 8; ++j) {
                s0[j] += __shfl_xor_sync(0xffffffffu, s0[j], 1);
                s0[j] += __shfl_xor_sync(0xffffffffu, s0[j], 2);
                s1[j] += __shfl_xor_sync(0xffffffffu, s1[j], 1);
                s1[j] += __shfl_xor_sync(0xffffffffu, s1[j], 2);
            }
            if (qc == 0) {
                float* d0 = scs + (r0 + qt) * 8;
                float* d1 = scs + (r0 + qt + 8) * 8;
                *(float4*)(d0)     = make_float4(softplus_fast(s0[0]), softplus_fast(s0[1]),
                                                 softplus_fast(s0[2]), softplus_fast(s0[3]));
                *(float4*)(d0 + 4) = make_float4(softplus_fast(s0[4]), softplus_fast(s0[5]),
                                                 softplus_fast(s0[6]), softplus_fast(s0[7]));
                *(float4*)(d1)     = make_float4(softplus_fast(s1[0]), softplus_fast(s1[1]),
                                                 softplus_fast(s1[2]), softplus_fast(s1[3]));
                *(float4*)(d1 + 4) = make_float4(softplus_fast(s1[4]), softplus_fast(s1[5]),
                                                 softplus_fast(s1[6]), softplus_fast(s1[7]));
            }
            __syncthreads();     // [scales barrier] release GEMM warps
        }

        __syncthreads();         // tile fence: epilogue done before Zf/scs reuse
    }
}

extern "C" void kernel_launch(void* const* d_in, const int* in_sizes, int n_in,
                              void* d_out, int out_size)
{
    const float* z    = (const float*)d_in[0];
    const float* w1   = (const float*)d_in[1];
    const float* b1   = (const float*)d_in[2];
    const float* w2   = (const float*)d_in[3];
    const float* b2   = (const float*)d_in[4];
    const float* w3   = (const float*)d_in[5];
    const float* mixw = (const float*)d_in[6];
    const float* gb   = (const float*)d_in[7];
    float* out = (float*)d_out;

    int Btot = in_sizes[0] / 128;                 // 524288 rows
    int nblocks = Btot / (ROWS * TILES);          // 1024

    prep_kernel<<<64, 256>>>(mixw);
    prep2_kernel<<<16, 256>>>(w2);

    static bool attr_set = false;
    if (!attr_set) {
        cudaFuncSetAttribute(soft_equivariant_kernel,
                             cudaFuncAttributeMaxDynamicSharedMemorySize, SMEM_BYTES);
        attr_set = true;
    }
    soft_equivariant_kernel<<<nblocks, THREADS, SMEM_BYTES>>>(
        z, w1, b1, b2, w3, gb, out);
}